// round 5
// baseline (speedup 1.0000x reference)
#include <cuda_runtime.h>
#include <cuda_bf16.h>
#include <cstdint>

// ---------------------------------------------------------------------------
// ConvTranspose4d: x[4,64,12,12,12,12] (*) w[64,64,3,3,3,3], stride 2, +bias
// out[4,64,25,25,25,25] fp32.
//
// R3: packed f32x2 FMAs (fma.rn.f32x2) pairing along co (weight pairs come
// directly from aligned float2 LDS, x scalars dup'd via mov.b64 on the idle
// ALU pipe), plus contiguous-o4 thread mapping so tap-a x loads are one
// LDS.128 per (ci,s) and tap-b reuses 3/4 of those registers (+1 LDS.32).
// Cuts FFMA pipe work 2x and smem crossbar traffic 25%.
// ---------------------------------------------------------------------------

#define CI 64
#define LI 12
#define XCI 20736            // 12^4
#define WSLICE 12288         // 64ci * 3k4 * 64co
#define OSTR_C 390625        // 25^4
#define XROW 16              // floats per (ci,s) x row (12 data + 4 zero pad)
#define XFLOATS (64 * 2 * XROW)   // 2048 floats = 8KB

__device__ float g_wt[27 * WSLICE];   // [k123][ci][k4][co]

// --- weight pre-transpose: w[ci][co][k1][k2][k3][k4] -> wt[k123][ci][k4][co]
__global__ void wtrans_kernel(const float* __restrict__ w) {
    int t = blockIdx.x * 256 + threadIdx.x;
    if (t >= 27 * WSLICE) return;
    int co   = t & 63;
    int k4   = (t >> 6) % 3;
    int ci   = (t / 192) & 63;
    int k123 = t / WSLICE;
    g_wt[t] = w[(size_t)(ci * 64 + co) * 81 + k123 * 3 + k4];
}

// ---- packed f32x2 helpers ----
__device__ __forceinline__ uint64_t dup2(float v) {
    uint64_t r; asm("mov.b64 %0, {%1, %1};" : "=l"(r) : "f"(v)); return r;
}
__device__ __forceinline__ uint64_t pk2(float a, float b) {
    uint64_t r; asm("mov.b64 %0, {%1, %2};" : "=l"(r) : "f"(a), "f"(b)); return r;
}
__device__ __forceinline__ void ffma2(uint64_t& d, uint64_t a, uint64_t b) {
    asm("fma.rn.f32x2 %0, %1, %2, %0;" : "+l"(d) : "l"(a), "l"(b));
}
__device__ __forceinline__ float2 unpk(uint64_t v) {
    float lo, hi; asm("mov.b64 {%0, %1}, %2;" : "=f"(lo), "=f"(hi) : "l"(v));
    return make_float2(lo, hi);
}

__device__ __forceinline__ void taps(int o, int& n, int* kl, int* il) {
    if (o & 1) { n = 1; kl[0] = 1; il[0] = (o - 1) >> 1; }
    else {
        n = 0; int ih = o >> 1;
        if (ih < LI)  { kl[n] = 0; il[n] = ih;     n++; }
        if (ih >= 1)  { kl[n] = 2; il[n] = ih - 1; n++; }
    }
}

// Inner loop. P = o4 parity. acc[s][j][q] is a (co_base+2q, co_base+2q+1) pair.
template <int P>
__device__ __forceinline__ void inner_loop(const float* __restrict__ ws,
                                           const float* __restrict__ xr,
                                           int cq, int m, int i4m1,
                                           uint64_t (&acc)[2][4][2]) {
    const float2* wsp = (const float2*)ws;
#pragma unroll 2
    for (int ci = 0; ci < CI; ++ci) {
        // weight pairs for this tap (aligned float2 -> 64-bit pair, no packing cost)
        float2 wa0f = wsp[(ci * 3 + P) * 32 + cq];
        float2 wa1f = wsp[(ci * 3 + P) * 32 + cq + 1];
        uint64_t wA0 = pk2(wa0f.x, wa0f.y);
        uint64_t wA1 = pk2(wa1f.x, wa1f.y);

        const float* row0 = xr + (ci * 2 + 0) * XROW;
        const float* row1 = xr + (ci * 2 + 1) * XROW;
        float4 x0 = *(const float4*)(row0 + 4 * m);   // tap-a x, s=0 (j=0..3)
        float4 x1 = *(const float4*)(row1 + 4 * m);   // tap-a x, s=1

        uint64_t d0[4] = {dup2(x0.x), dup2(x0.y), dup2(x0.z), dup2(x0.w)};
        uint64_t d1[4] = {dup2(x1.x), dup2(x1.y), dup2(x1.z), dup2(x1.w)};

#pragma unroll
        for (int j = 0; j < 4; ++j) {
            ffma2(acc[0][j][0], wA0, d0[j]); ffma2(acc[0][j][1], wA1, d0[j]);
            ffma2(acc[1][j][0], wA0, d1[j]); ffma2(acc[1][j][1], wA1, d1[j]);
        }

        if (P == 0) {  // second tap k4=2: i4 = t-1, reuses d[j-1], one new scalar
            float2 wb0f = wsp[(ci * 3 + 2) * 32 + cq];
            float2 wb1f = wsp[(ci * 3 + 2) * 32 + cq + 1];
            uint64_t wB0 = pk2(wb0f.x, wb0f.y);
            uint64_t wB1 = pk2(wb1f.x, wb1f.y);
            uint64_t e0 = dup2(row0[i4m1]);
            uint64_t e1 = dup2(row1[i4m1]);

            ffma2(acc[0][0][0], wB0, e0); ffma2(acc[0][0][1], wB1, e0);
            ffma2(acc[1][0][0], wB0, e1); ffma2(acc[1][0][1], wB1, e1);
#pragma unroll
            for (int j = 1; j < 4; ++j) {
                ffma2(acc[0][j][0], wB0, d0[j - 1]); ffma2(acc[0][j][1], wB1, d0[j - 1]);
                ffma2(acc[1][j][0], wB0, d1[j - 1]); ffma2(acc[1][j][1], wB1, d1[j - 1]);
            }
        }
    }
}

__global__ void __launch_bounds__(128, 4)
convt4d_kernel(const float* __restrict__ x,
               const float* __restrict__ bias,
               float* __restrict__ out) {
    extern __shared__ float smem[];
    float* ws  = smem;                 // 12288 floats: [ci][k4][co]
    float* xsf = smem + WSLICE;        // 2048 floats: [ci][s][16]

    const int bid = blockIdx.x;
    const int tid = threadIdx.x;

    int o3g = bid % 13;
    int r   = bid / 13;
    const int o2 = r % 25; r /= 25;
    const int o1 = r % 25;
    const int b  = r / 25;

    int n1, k1l[2], i1l[2]; taps(o1, n1, k1l, i1l);
    int n2, k2l[2], i2l[2]; taps(o2, n2, k2l, i2l);

    // o3 same-parity pair
    int o3a, o3b; bool bvalid;
    if (o3g < 7) { o3a = 4 * o3g;        o3b = o3a + 2; bvalid = (o3b <= 24); }
    else         { o3a = 4 * (o3g - 7) + 1; o3b = o3a + 2; bvalid = true; }

    int n3, k3l[2], i3l[2][2];
    if (o3a & 1) {
        n3 = 1; k3l[0] = 1;
        i3l[0][0] = (o3a - 1) >> 1;
        i3l[0][1] = bvalid ? ((o3b - 1) >> 1) : -1;
    } else {
        n3 = 0;
        { int ia = o3a >> 1; int ib = bvalid ? (o3b >> 1) : LI;
          if (ia < LI || ib < LI) {
              k3l[n3] = 0;
              i3l[n3][0] = (ia < LI) ? ia : -1;
              i3l[n3][1] = (bvalid && ib < LI) ? ib : -1;
              n3++; } }
        { int ia = (o3a >> 1) - 1; int ib = bvalid ? ((o3b >> 1) - 1) : -1;
          if (ia >= 0 || ib >= 0) {
              k3l[n3] = 2;
              i3l[n3][0] = (ia >= 0) ? ia : -1;
              i3l[n3][1] = (bvalid && ib >= 0) ? ib : -1;
              n3++; } }
    }

    // thread mapping: parity-pure warps (wave-swizzled), contiguous o4 per thread
    const int wrp = tid >> 5, lane = tid & 31;
    const int psw = (bid / 148) & 1;
    const int p   = (wrp & 1) ^ psw;               // o4 parity this warp owns
    const int cl  = (wrp >> 1) * 8 + (lane >> 2);  // [0,16) co group
    const int m   = lane & 3;                      // [0,4): t = 4m+j
    const int co_base = cl * 4;
    const int cq  = cl * 2;                        // float2 index of co_base
    const int i4m1 = (m == 0) ? 15 : (4 * m - 1);  // slot 15 is always zero

    uint64_t acc[2][4][2];
#pragma unroll
    for (int s = 0; s < 2; ++s)
#pragma unroll
        for (int j = 0; j < 4; ++j) { acc[s][j][0] = 0ull; acc[s][j][1] = 0ull; }

    // zero-fill pad slots 12..15 of every (ci,s) row once (staging writes 0..11)
    {
        float4 z = make_float4(0.f, 0.f, 0.f, 0.f);
        *(float4*)(xsf + tid * XROW + 12) = z;     // tid == ci*2+s, exactly 128 rows
    }

    for (int t3 = 0; t3 < n3; ++t3)
    for (int t2 = 0; t2 < n2; ++t2)
    for (int t1 = 0; t1 < n1; ++t1) {
        const int k123 = (k1l[t1] * 3 + k2l[t2]) * 3 + k3l[t3];
        __syncthreads();   // previous compute done before restage

        // stage weights: contiguous float4 copy from pre-transposed scratch
        {
            const float4* gw = (const float4*)(g_wt + (size_t)k123 * WSLICE);
            float4* sw = (float4*)ws;
#pragma unroll 6
            for (int idx = tid; idx < WSLICE / 4; idx += 128) sw[idx] = gw[idx];
        }
        // stage inputs: [ci][s][0..11]
        {
            const int i1v = i1l[t1], i2v = i2l[t2];
            const int i30 = i3l[t3][0], i31 = i3l[t3][1];
            const int xoff12 = i1v * 1728 + i2v * 144;
#pragma unroll
            for (int idx = tid; idx < 384; idx += 128) {
                int v  = idx % 3;
                int s  = (idx / 3) & 1;
                int ci = idx / 6;
                int i3 = s ? i31 : i30;
                float4 val = make_float4(0.f, 0.f, 0.f, 0.f);
                if (i3 >= 0)
                    val = *(const float4*)(x + (size_t)(b * 64 + ci) * XCI
                                             + xoff12 + i3 * 12 + v * 4);
                *(float4*)(xsf + (ci * 2 + s) * XROW + 4 * v) = val;
            }
        }
        __syncthreads();

        if (p == 0) inner_loop<0>(ws, xsf, cq, m, i4m1, acc);
        else        inner_loop<1>(ws, xsf, cq, m, i4m1, acc);
    }

    // epilogue: + bias, streaming stores
    const float4 bv = *(const float4*)(bias + co_base);
#pragma unroll
    for (int s = 0; s < 2; ++s) {
        if (s == 1 && !bvalid) break;
        const int o3 = s ? o3b : o3a;
        const size_t base0 =
            ((((size_t)(b * 64 + co_base) * 25 + o1) * 25 + o2) * 25 + o3) * 25;
#pragma unroll
        for (int j = 0; j < 4; ++j) {
            const int o4 = 8 * m + 2 * j + p;
            if (o4 > 24) continue;
            float2 v0 = unpk(acc[s][j][0]);
            float2 v1 = unpk(acc[s][j][1]);
            const size_t base = base0 + o4;
            __stcs(out + base + 0 * (size_t)OSTR_C, v0.x + bv.x);
            __stcs(out + base + 1 * (size_t)OSTR_C, v0.y + bv.y);
            __stcs(out + base + 2 * (size_t)OSTR_C, v1.x + bv.z);
            __stcs(out + base + 3 * (size_t)OSTR_C, v1.y + bv.w);
        }
    }
}

extern "C" void kernel_launch(void* const* d_in, const int* in_sizes, int n_in,
                              void* d_out, int out_size) {
    const float* x    = (const float*)d_in[0];
    const float* wgt  = (const float*)d_in[1];
    const float* bias = (const float*)d_in[2];
    float* out        = (float*)d_out;

    wtrans_kernel<<<(27 * WSLICE + 255) / 256, 256>>>(wgt);

    const int smem_bytes = (WSLICE + XFLOATS) * sizeof(float);  // 57344 = 56KB
    cudaFuncSetAttribute(convt4d_kernel,
                         cudaFuncAttributeMaxDynamicSharedMemorySize, smem_bytes);

    const int nblocks = 4 * 25 * 25 * 13;  // (b, o1, o2, o3-pair-group)
    convt4d_kernel<<<nblocks, 128, smem_bytes>>>(x, bias, out);
}